// round 1
// baseline (speedup 1.0000x reference)
#include <cuda_runtime.h>
#include <math.h>

#define H 64
#define NB 8
#define NL 2
#define MAXN 50000
#define MAXE 800000

// ---------------- scratch (device globals; no allocation allowed) ------------
__device__ float g_x[MAXN * H];
__device__ float g_P[MAXN * H];
__device__ float g_Q[MAXN * H];
__device__ float g_aggH[MAXN * H];
__device__ float g_agg[MAXN * H];
__device__ float g_ea[MAXE * NB];
__device__ float g_deg[MAXN];

__device__ __forceinline__ float silu(float v) {
    return v / (1.0f + __expf(-v));
}

// ---------------- utility: zero a buffer ------------------------------------
__global__ void k_zero(float* __restrict__ p, int n) {
    int i = blockIdx.x * blockDim.x + threadIdx.x;
    int stride = gridDim.x * blockDim.x;
    for (; i < n; i += stride) p[i] = 0.0f;
}

// ---------------- x = embed[z] -----------------------------------------------
__global__ void k_init_x(const int* __restrict__ z, const float* __restrict__ embed, int N) {
    int i = blockIdx.x * blockDim.x + threadIdx.x;
    int stride = gridDim.x * blockDim.x;
    int total = N * H;
    for (; i < total; i += stride) {
        int n = i >> 6, h = i & 63;
        g_x[i] = embed[z[n] * H + h];
    }
}

// ---------------- edge_attr (E x 8) + degree ---------------------------------
__global__ void k_edge_attr(const int* __restrict__ ei, const float* __restrict__ pos, int E) {
    int e = blockIdx.x * blockDim.x + threadIdx.x;
    int stride = gridDim.x * blockDim.x;
    const float PI = 3.14159265358979323846f;
    for (; e < E; e += stride) {
        int r = ei[e], c = ei[E + e];
        float dx = pos[r * 3 + 0] - pos[c * 3 + 0];
        float dy = pos[r * 3 + 1] - pos[c * 3 + 1];
        float dz = pos[r * 3 + 2] - pos[c * 3 + 2];
        float d = sqrtf(dx * dx + dy * dy + dz * dz);
        float env = 0.0f;
        if (d < 5.0f) {
            float cv = cosf(d * (PI / 10.0f));
            env = cv * cv;
        }
        float dsafe = (d > 0.0f) ? d : 1.0f;
        float inv = env / dsafe;
#pragma unroll
        for (int j = 0; j < NB; j++) {
            g_ea[e * NB + j] = sinf((float)(j + 1) * (PI / 5.0f) * d) * inv;
        }
        atomicAdd(&g_deg[c], 1.0f);
    }
}

// ---------------- P = x @ W1[0:64], Q = x @ W1[64:128] -----------------------
// one warp computes 4 rows x 128 output cols (P cols 0..63, Q cols 64..127)
__global__ void k_pq(const float* __restrict__ w1, int N) {
    __shared__ float sB[64 * 128];
    __shared__ float sA[8][4 * 64];

    for (int idx = threadIdx.x; idx < 64 * 128; idx += blockDim.x) {
        int k = idx >> 7, j = idx & 127;
        sB[idx] = (j < 64) ? w1[k * 64 + j] : w1[(64 + k) * 64 + (j - 64)];
    }
    __syncthreads();

    int warp = threadIdx.x >> 5, lane = threadIdx.x & 31;
    int gw = (blockIdx.x * blockDim.x + threadIdx.x) >> 5;
    int nw = (gridDim.x * blockDim.x) >> 5;

    for (int r0 = gw * 4; r0 < N; r0 += nw * 4) {
        int nr = min(4, N - r0);
        for (int t = lane; t < nr * 64; t += 32) sA[warp][t] = g_x[r0 * 64 + t];
        __syncwarp();

        float acc[4][4];
#pragma unroll
        for (int rr = 0; rr < 4; rr++)
#pragma unroll
            for (int c = 0; c < 4; c++) acc[rr][c] = 0.0f;

#pragma unroll 4
        for (int k = 0; k < 64; k++) {
            float b0 = sB[k * 128 + lane];
            float b1 = sB[k * 128 + lane + 32];
            float b2 = sB[k * 128 + lane + 64];
            float b3 = sB[k * 128 + lane + 96];
#pragma unroll
            for (int rr = 0; rr < 4; rr++) {
                float a = sA[warp][rr * 64 + k];
                acc[rr][0] += a * b0;
                acc[rr][1] += a * b1;
                acc[rr][2] += a * b2;
                acc[rr][3] += a * b3;
            }
        }
        for (int rr = 0; rr < nr; rr++) {
            int base = (r0 + rr) * 64;
            g_P[base + lane] = acc[rr][0];
            g_P[base + lane + 32] = acc[rr][1];
            g_Q[base + lane] = acc[rr][2];
            g_Q[base + lane + 32] = acc[rr][3];
        }
        __syncwarp();
    }
}

// ---------------- edge phase: aggH[col] += silu(P[col]+Q[row]+ea@W1c+b1) ------
__global__ void k_edge(const int* __restrict__ ei, const float* __restrict__ w1,
                       const float* __restrict__ b1, int E) {
    __shared__ float sWc[NB * 64];
    __shared__ float sb1[64];
    for (int idx = threadIdx.x; idx < NB * 64; idx += blockDim.x)
        sWc[idx] = w1[128 * 64 + idx];  // rows 128..135 are contiguous
    if (threadIdx.x < 64) sb1[threadIdx.x] = b1[threadIdx.x];
    __syncthreads();

    int lane = threadIdx.x & 31;
    int gw = (blockIdx.x * blockDim.x + threadIdx.x) >> 5;
    int nw = (gridDim.x * blockDim.x) >> 5;

    for (int e = gw; e < E; e += nw) {
        int r = ei[e], c = ei[E + e];
        float ea[NB];
#pragma unroll
        for (int j = 0; j < NB; j++) ea[j] = g_ea[e * NB + j];

        float p0 = g_P[c * 64 + lane] + g_Q[r * 64 + lane] + sb1[lane];
        float p1 = g_P[c * 64 + lane + 32] + g_Q[r * 64 + lane + 32] + sb1[lane + 32];
#pragma unroll
        for (int j = 0; j < NB; j++) {
            p0 += ea[j] * sWc[j * 64 + lane];
            p1 += ea[j] * sWc[j * 64 + lane + 32];
        }
        atomicAdd(&g_aggH[c * 64 + lane], silu(p0));
        atomicAdd(&g_aggH[c * 64 + lane + 32], silu(p1));
    }
}

// ---------------- agg = aggH @ W2 + deg * b2 ----------------------------------
__global__ void k_w2(const float* __restrict__ w2, const float* __restrict__ b2, int N) {
    __shared__ float sB[64 * 64];
    __shared__ float sb[64];
    __shared__ float sA[8][4 * 64];

    for (int idx = threadIdx.x; idx < 64 * 64; idx += blockDim.x) sB[idx] = w2[idx];
    if (threadIdx.x < 64) sb[threadIdx.x] = b2[threadIdx.x];
    __syncthreads();

    int warp = threadIdx.x >> 5, lane = threadIdx.x & 31;
    int gw = (blockIdx.x * blockDim.x + threadIdx.x) >> 5;
    int nw = (gridDim.x * blockDim.x) >> 5;

    for (int r0 = gw * 4; r0 < N; r0 += nw * 4) {
        int nr = min(4, N - r0);
        for (int t = lane; t < nr * 64; t += 32) sA[warp][t] = g_aggH[r0 * 64 + t];
        __syncwarp();

        float acc[4][2];
#pragma unroll
        for (int rr = 0; rr < 4; rr++) { acc[rr][0] = 0.0f; acc[rr][1] = 0.0f; }

#pragma unroll 4
        for (int k = 0; k < 64; k++) {
            float b0 = sB[k * 64 + lane];
            float b1 = sB[k * 64 + lane + 32];
#pragma unroll
            for (int rr = 0; rr < 4; rr++) {
                float a = sA[warp][rr * 64 + k];
                acc[rr][0] += a * b0;
                acc[rr][1] += a * b1;
            }
        }
        for (int rr = 0; rr < nr; rr++) {
            int base = (r0 + rr) * 64;
            float dg = g_deg[r0 + rr];
            g_agg[base + lane] = acc[rr][0] + dg * sb[lane];
            g_agg[base + lane + 32] = acc[rr][1] + dg * sb[lane + 32];
        }
        __syncwarp();
    }
}

// ---------------- fused update: x += silu([x,agg]@uW1+b1)@uW2+b2 --------------
// dynamic shared; one warp handles 2 rows
__global__ void k_update(const float* __restrict__ uw1, const float* __restrict__ ub1,
                         const float* __restrict__ uw2, const float* __restrict__ ub2, int N) {
    extern __shared__ float sm[];
    float* sW1 = sm;              // 128*64 = 8192
    float* sW2 = sm + 8192;       // 64*64  = 4096
    float* sb1 = sm + 12288;      // 64
    float* sb2 = sm + 12352;      // 64
    float* sIn = sm + 12416;      // 8 warps * 2 rows * 128 = 2048
    float* sHid = sm + 14464;     // 8 warps * 2 rows * 64  = 1024

    for (int idx = threadIdx.x; idx < 8192; idx += blockDim.x) sW1[idx] = uw1[idx];
    for (int idx = threadIdx.x; idx < 4096; idx += blockDim.x) sW2[idx] = uw2[idx];
    if (threadIdx.x < 64) { sb1[threadIdx.x] = ub1[threadIdx.x]; sb2[threadIdx.x] = ub2[threadIdx.x]; }
    __syncthreads();

    int warp = threadIdx.x >> 5, lane = threadIdx.x & 31;
    int gw = (blockIdx.x * blockDim.x + threadIdx.x) >> 5;
    int nw = (gridDim.x * blockDim.x) >> 5;
    float* in = sIn + warp * 256;
    float* hid = sHid + warp * 128;

    for (int r0 = gw * 2; r0 < N; r0 += nw * 2) {
        int nr = min(2, N - r0);
        for (int rr = 0; rr < nr; rr++) {
            int base = (r0 + rr) * 64;
            for (int t = lane; t < 128; t += 32)
                in[rr * 128 + t] = (t < 64) ? g_x[base + t] : g_agg[base + t - 64];
        }
        __syncwarp();

        float acc[2][2];
#pragma unroll
        for (int rr = 0; rr < 2; rr++) { acc[rr][0] = sb1[lane]; acc[rr][1] = sb1[lane + 32]; }

#pragma unroll 4
        for (int k = 0; k < 128; k++) {
            float w0 = sW1[k * 64 + lane];
            float w1v = sW1[k * 64 + lane + 32];
#pragma unroll
            for (int rr = 0; rr < 2; rr++) {
                float a = in[rr * 128 + k];
                acc[rr][0] += a * w0;
                acc[rr][1] += a * w1v;
            }
        }
#pragma unroll
        for (int rr = 0; rr < 2; rr++) {
            hid[rr * 64 + lane] = silu(acc[rr][0]);
            hid[rr * 64 + lane + 32] = silu(acc[rr][1]);
        }
        __syncwarp();

        float o[2][2];
#pragma unroll
        for (int rr = 0; rr < 2; rr++) { o[rr][0] = sb2[lane]; o[rr][1] = sb2[lane + 32]; }

#pragma unroll 4
        for (int k = 0; k < 64; k++) {
            float w0 = sW2[k * 64 + lane];
            float w1v = sW2[k * 64 + lane + 32];
#pragma unroll
            for (int rr = 0; rr < 2; rr++) {
                float a = hid[rr * 64 + k];
                o[rr][0] += a * w0;
                o[rr][1] += a * w1v;
            }
        }
        for (int rr = 0; rr < nr; rr++) {
            int base = (r0 + rr) * 64;
            g_x[base + lane] += o[rr][0];
            g_x[base + lane + 32] += o[rr][1];
        }
        __syncwarp();
    }
}

// ---------------- readout: energy[batch[n]] += silu(x@W1+b1)@w2 + b2 ----------
__global__ void k_readout(const float* __restrict__ w1, const float* __restrict__ b1,
                          const float* __restrict__ w2, const float* __restrict__ b2,
                          const int* __restrict__ batch, float* __restrict__ out, int N) {
    __shared__ float sW1[64 * 64];
    __shared__ float sb1[64];
    __shared__ float sw2[64];
    __shared__ float sb2s;
    __shared__ float sA[8][2 * 64];

    for (int idx = threadIdx.x; idx < 64 * 64; idx += blockDim.x) sW1[idx] = w1[idx];
    if (threadIdx.x < 64) { sb1[threadIdx.x] = b1[threadIdx.x]; sw2[threadIdx.x] = w2[threadIdx.x]; }
    if (threadIdx.x == 0) sb2s = b2[0];
    __syncthreads();

    int warp = threadIdx.x >> 5, lane = threadIdx.x & 31;
    int gw = (blockIdx.x * blockDim.x + threadIdx.x) >> 5;
    int nw = (gridDim.x * blockDim.x) >> 5;

    for (int r0 = gw * 2; r0 < N; r0 += nw * 2) {
        int nr = min(2, N - r0);
        for (int t = lane; t < nr * 64; t += 32) sA[warp][t] = g_x[r0 * 64 + t];
        __syncwarp();

        float acc[2][2];
#pragma unroll
        for (int rr = 0; rr < 2; rr++) { acc[rr][0] = sb1[lane]; acc[rr][1] = sb1[lane + 32]; }

#pragma unroll 4
        for (int k = 0; k < 64; k++) {
            float w0 = sW1[k * 64 + lane];
            float w1v = sW1[k * 64 + lane + 32];
#pragma unroll
            for (int rr = 0; rr < 2; rr++) {
                float a = sA[warp][rr * 64 + k];
                acc[rr][0] += a * w0;
                acc[rr][1] += a * w1v;
            }
        }
        float pe[2];
#pragma unroll
        for (int rr = 0; rr < 2; rr++) {
            pe[rr] = silu(acc[rr][0]) * sw2[lane] + silu(acc[rr][1]) * sw2[lane + 32];
#pragma unroll
            for (int off = 16; off > 0; off >>= 1)
                pe[rr] += __shfl_xor_sync(0xFFFFFFFF, pe[rr], off);
        }
        if (lane == 0) {
            for (int rr = 0; rr < nr; rr++)
                atomicAdd(&out[batch[r0 + rr]], pe[rr] + sb2s);
        }
        __syncwarp();
    }
}

// ------------------------------- host side ------------------------------------
extern "C" void kernel_launch(void* const* d_in, const int* in_sizes, int n_in,
                              void* d_out, int out_size) {
    const int* z = (const int*)d_in[0];
    const float* pos = (const float*)d_in[1];
    const int* ei = (const int*)d_in[2];
    const int* batch = (const int*)d_in[3];
    const float* embed = (const float*)d_in[4];
    const float* msg_w1 = (const float*)d_in[5];
    const float* msg_b1 = (const float*)d_in[6];
    const float* msg_w2 = (const float*)d_in[7];
    const float* msg_b2 = (const float*)d_in[8];
    const float* upd_w1 = (const float*)d_in[9];
    const float* upd_b1 = (const float*)d_in[10];
    const float* upd_w2 = (const float*)d_in[11];
    const float* upd_b2 = (const float*)d_in[12];
    const float* eh_w1 = (const float*)d_in[13];
    const float* eh_b1 = (const float*)d_in[14];
    const float* eh_w2 = (const float*)d_in[15];
    const float* eh_b2 = (const float*)d_in[16];
    float* out = (float*)d_out;

    int N = in_sizes[0];
    int E = in_sizes[2] / 2;

    float* p_aggH; cudaGetSymbolAddress((void**)&p_aggH, g_aggH);
    float* p_deg;  cudaGetSymbolAddress((void**)&p_deg, g_deg);

    static bool attr_set = false;
    if (!attr_set) {
        cudaFuncSetAttribute(k_update, cudaFuncAttributeMaxDynamicSharedMemorySize, 15488 * 4);
        attr_set = true;
    }

    const int TPB = 256;
    const int NBLK = 1184;   // node-parallel kernels (grid-stride)
    const int EBLK = 2368;   // edge-parallel kernels (grid-stride)

    // prologue
    k_zero<<<64, TPB>>>(p_deg, N);
    k_init_x<<<NBLK, TPB>>>(z, embed, N);
    k_edge_attr<<<EBLK, TPB>>>(ei, pos, E);

    for (int l = 0; l < NL; l++) {
        const float* w1 = msg_w1 + l * 136 * 64;
        const float* b1 = msg_b1 + l * 64;
        const float* w2 = msg_w2 + l * 64 * 64;
        const float* b2 = msg_b2 + l * 64;
        const float* uw1 = upd_w1 + l * 128 * 64;
        const float* ub1 = upd_b1 + l * 64;
        const float* uw2 = upd_w2 + l * 64 * 64;
        const float* ub2 = upd_b2 + l * 64;

        k_zero<<<NBLK, TPB>>>(p_aggH, N * H);
        k_pq<<<NBLK, TPB>>>(w1, N);
        k_edge<<<EBLK, TPB>>>(ei, w1, b1, E);
        k_w2<<<NBLK, TPB>>>(w2, b2, N);
        k_update<<<NBLK, TPB, 15488 * 4>>>(uw1, ub1, uw2, ub2, N);
    }

    // readout
    k_zero<<<1, 64>>>(out, out_size);
    k_readout<<<NBLK, TPB>>>(eh_w1, eh_b1, eh_w2, eh_b2, batch, out, N);
}

// round 2
// speedup vs baseline: 1.3866x; 1.3866x over previous
#include <cuda_runtime.h>
#include <math.h>

#define H 64
#define NB 8
#define NL 2
#define MAXN 50000
#define MAXE 800000

// ---------------- scratch (device globals; no allocation allowed) ------------
__device__ __align__(256) float g_x[MAXN * H];
__device__ __align__(256) float g_P[MAXN * H];     // x@W1a + b1
__device__ __align__(256) float g_Q[MAXN * H];     // x@W1b
__device__ __align__(256) float g_aggH[MAXN * H];
__device__ __align__(256) float g_ea[MAXE * NB];
__device__ __align__(256) float g_deg[MAXN];

__device__ __forceinline__ float silu(float v) {
    return __fdividef(v, 1.0f + __expf(-v));
}

// ---------------- utility: zero a buffer ------------------------------------
__global__ void k_zero(float* __restrict__ p, int n) {
    int i = blockIdx.x * blockDim.x + threadIdx.x;
    int stride = gridDim.x * blockDim.x;
    for (; i < n; i += stride) p[i] = 0.0f;
}

// ---------------- x = embed[z] (float2 vectorized) ----------------------------
__global__ void k_init_x(const int* __restrict__ z, const float* __restrict__ embed, int N) {
    int i = blockIdx.x * blockDim.x + threadIdx.x;
    int stride = gridDim.x * blockDim.x;
    int total = N * 32;  // float2 units
    float2* x2 = (float2*)g_x;
    const float2* e2 = (const float2*)embed;
    for (; i < total; i += stride) {
        int n = i >> 5, h = i & 31;
        x2[i] = e2[z[n] * 32 + h];
    }
}

// ---------------- edge_attr (E x 8) + degree: sincos + Chebyshev --------------
__global__ void k_edge_attr(const int* __restrict__ ei, const float* __restrict__ pos, int E) {
    int e = blockIdx.x * blockDim.x + threadIdx.x;
    int stride = gridDim.x * blockDim.x;
    const float PI = 3.14159265358979323846f;
    float4* ea4 = (float4*)g_ea;
    for (; e < E; e += stride) {
        int r = ei[e], c = ei[E + e];
        float dx = pos[r * 3 + 0] - pos[c * 3 + 0];
        float dy = pos[r * 3 + 1] - pos[c * 3 + 1];
        float dz = pos[r * 3 + 2] - pos[c * 3 + 2];
        float d = sqrtf(dx * dx + dy * dy + dz * dz);
        float env = 0.0f;
        if (d < 5.0f) {
            float cv = __cosf(d * (PI / 10.0f));
            env = cv * cv;
        }
        float inv = __fdividef(env, (d > 0.0f) ? d : 1.0f);
        float s1, c1;
        __sincosf(d * (PI / 5.0f), &s1, &c1);
        float twoc = 2.0f * c1;
        float sp = 0.0f, sc = s1;   // sin(k*theta) recurrence
        float v[NB];
#pragma unroll
        for (int j = 0; j < NB; j++) {
            v[j] = sc * inv;
            float sn = twoc * sc - sp;
            sp = sc; sc = sn;
        }
        ea4[e * 2 + 0] = make_float4(v[0], v[1], v[2], v[3]);
        ea4[e * 2 + 1] = make_float4(v[4], v[5], v[6], v[7]);
        atomicAdd(&g_deg[c], 1.0f);
    }
}

// ---------------- P = x@W1a + b1, Q = x@W1b; also zero aggH --------------------
__global__ void k_pq(const float* __restrict__ w1, const float* __restrict__ b1, int N) {
    __shared__ float2 sB[64 * 64];   // [k][c2]: c2<32 -> P col pair, c2>=32 -> Q col pair
    __shared__ float2 sb1[32];
    __shared__ float sA[8][4 * 64];

    const float2* w1v = (const float2*)w1;
    for (int u = threadIdx.x; u < 64 * 64; u += blockDim.x) {
        int k = u >> 6, c2 = u & 63;
        sB[u] = (c2 < 32) ? w1v[k * 32 + c2] : w1v[(64 + k) * 32 + (c2 - 32)];
    }
    if (threadIdx.x < 32) sb1[threadIdx.x] = ((const float2*)b1)[threadIdx.x];
    __syncthreads();

    int warp = threadIdx.x >> 5, lane = threadIdx.x & 31;
    int gw = (blockIdx.x * blockDim.x + threadIdx.x) >> 5;
    int nw = (gridDim.x * blockDim.x) >> 5;

    float2* P2 = (float2*)g_P;
    float2* Q2 = (float2*)g_Q;
    float2* Z2 = (float2*)g_aggH;
    const float2* X2 = (const float2*)g_x;

    for (int r0 = gw * 4; r0 < N; r0 += nw * 4) {
        int nr = min(4, N - r0);
        for (int t = lane; t < nr * 32; t += 32)
            ((float2*)sA[warp])[t] = X2[r0 * 32 + t];
        __syncwarp();

        float2 bb = sb1[lane];
        float2 aP[4], aQ[4];
#pragma unroll
        for (int rr = 0; rr < 4; rr++) { aP[rr] = bb; aQ[rr] = make_float2(0.f, 0.f); }

#pragma unroll 8
        for (int k = 0; k < 64; k++) {
            float2 bP = sB[k * 64 + lane];
            float2 bQ = sB[k * 64 + 32 + lane];
#pragma unroll
            for (int rr = 0; rr < 4; rr++) {
                float a = sA[warp][rr * 64 + k];
                aP[rr].x = fmaf(a, bP.x, aP[rr].x);
                aP[rr].y = fmaf(a, bP.y, aP[rr].y);
                aQ[rr].x = fmaf(a, bQ.x, aQ[rr].x);
                aQ[rr].y = fmaf(a, bQ.y, aQ[rr].y);
            }
        }
        for (int rr = 0; rr < nr; rr++) {
            int b = (r0 + rr) * 32 + lane;
            P2[b] = aP[rr];
            Q2[b] = aQ[rr];
            Z2[b] = make_float2(0.f, 0.f);
        }
        __syncwarp();
    }
}

// ---------------- edge phase: aggH[c] += silu(P[c]+Q[r]+ea@W1c) ----------------
__global__ void k_edge(const int* __restrict__ ei, const float* __restrict__ w1, int E) {
    __shared__ float2 sWc[NB * 32];
    for (int u = threadIdx.x; u < NB * 32; u += blockDim.x)
        sWc[u] = ((const float2*)w1)[128 * 32 + u];   // rows 128..135, contiguous
    __syncthreads();

    int lane = threadIdx.x & 31;
    int gw = (blockIdx.x * blockDim.x + threadIdx.x) >> 5;
    int nw = (gridDim.x * blockDim.x) >> 5;

    const float2* P2 = (const float2*)g_P;
    const float2* Q2 = (const float2*)g_Q;
    const float4* ea4 = (const float4*)g_ea;

    for (int e = gw; e < E; e += nw) {
        int r = __ldg(&ei[e]), c = __ldg(&ei[E + e]);
        float4 eA = __ldg(&ea4[e * 2 + 0]);
        float4 eB = __ldg(&ea4[e * 2 + 1]);
        float2 p = P2[c * 32 + lane];
        float2 q = Q2[r * 32 + lane];
        float vx = p.x + q.x, vy = p.y + q.y;
        float2 w;
        w = sWc[0 * 32 + lane]; vx = fmaf(eA.x, w.x, vx); vy = fmaf(eA.x, w.y, vy);
        w = sWc[1 * 32 + lane]; vx = fmaf(eA.y, w.x, vx); vy = fmaf(eA.y, w.y, vy);
        w = sWc[2 * 32 + lane]; vx = fmaf(eA.z, w.x, vx); vy = fmaf(eA.z, w.y, vy);
        w = sWc[3 * 32 + lane]; vx = fmaf(eA.w, w.x, vx); vy = fmaf(eA.w, w.y, vy);
        w = sWc[4 * 32 + lane]; vx = fmaf(eB.x, w.x, vx); vy = fmaf(eB.x, w.y, vy);
        w = sWc[5 * 32 + lane]; vx = fmaf(eB.y, w.x, vx); vy = fmaf(eB.y, w.y, vy);
        w = sWc[6 * 32 + lane]; vx = fmaf(eB.z, w.x, vx); vy = fmaf(eB.z, w.y, vy);
        w = sWc[7 * 32 + lane]; vx = fmaf(eB.w, w.x, vx); vy = fmaf(eB.w, w.y, vy);
        float mx = silu(vx), my = silu(vy);
        float* dst = g_aggH + (size_t)c * 64 + 2 * lane;
        asm volatile("red.global.add.v2.f32 [%0], {%1, %2};"
                     :: "l"(dst), "f"(mx), "f"(my) : "memory");
    }
}

// ---------------- fused node phase: agg=aggH@W2+deg*b2; x+=upd; [readout] ------
__global__ void k_node(const float* __restrict__ w2, const float* __restrict__ b2,
                       const float* __restrict__ uw1, const float* __restrict__ ub1,
                       const float* __restrict__ uw2, const float* __restrict__ ub2,
                       const float* __restrict__ ew1, const float* __restrict__ eb1,
                       const float* __restrict__ ew2, const float* __restrict__ eb2,
                       const int* __restrict__ batch, float* __restrict__ out,
                       int N, int do_readout) {
    extern __shared__ float sm[];
    float2* sW2  = (float2*)sm;          // 2048 f2
    float2* sUW1 = sW2 + 2048;           // 4096 f2
    float2* sUW2 = sUW1 + 4096;          // 2048 f2
    float2* sEW1 = sUW2 + 2048;          // 2048 f2
    float2* sb2v  = sEW1 + 2048;         // 32
    float2* sub1v = sb2v + 32;
    float2* sub2v = sub1v + 32;
    float2* seb1v = sub2v + 32;
    float2* sew2v = seb1v + 32;          // 32
    float* sEb2 = sm + 20800;            // 64 floats (only [0] used)
    float* sIn  = sm + 20864;            // 8 warps * 256
    float* sHid = sm + 22912;            // 8 warps * 128

    for (int u = threadIdx.x; u < 2048; u += blockDim.x) sW2[u]  = ((const float2*)w2)[u];
    for (int u = threadIdx.x; u < 4096; u += blockDim.x) sUW1[u] = ((const float2*)uw1)[u];
    for (int u = threadIdx.x; u < 2048; u += blockDim.x) sUW2[u] = ((const float2*)uw2)[u];
    if (do_readout)
        for (int u = threadIdx.x; u < 2048; u += blockDim.x) sEW1[u] = ((const float2*)ew1)[u];
    if (threadIdx.x < 32) {
        sb2v[threadIdx.x]  = ((const float2*)b2)[threadIdx.x];
        sub1v[threadIdx.x] = ((const float2*)ub1)[threadIdx.x];
        sub2v[threadIdx.x] = ((const float2*)ub2)[threadIdx.x];
        if (do_readout) {
            seb1v[threadIdx.x] = ((const float2*)eb1)[threadIdx.x];
            sew2v[threadIdx.x] = ((const float2*)ew2)[threadIdx.x];
        }
    }
    if (threadIdx.x == 0) sEb2[0] = do_readout ? eb2[0] : 0.0f;
    __syncthreads();

    int warp = threadIdx.x >> 5, lane = threadIdx.x & 31;
    int gw = (blockIdx.x * blockDim.x + threadIdx.x) >> 5;
    int nw = (gridDim.x * blockDim.x) >> 5;
    float* in  = sIn + warp * 256;
    float* hid = sHid + warp * 128;

    const float2* X2r = (const float2*)g_x;
    float2* X2w = (float2*)g_x;
    const float2* AG2 = (const float2*)g_aggH;

    for (int r0 = gw * 2; r0 < N; r0 += nw * 2) {
        int nr = min(2, N - r0);

        // --- phase A: agg = aggH @ W2 + deg*b2 ---
        for (int t = lane; t < nr * 32; t += 32)
            ((float2*)hid)[t] = AG2[r0 * 32 + t];
        __syncwarp();

        float2 agg[2] = {make_float2(0.f, 0.f), make_float2(0.f, 0.f)};
#pragma unroll 8
        for (int k = 0; k < 64; k++) {
            float2 b = sW2[k * 32 + lane];
            float a0 = hid[k];
            float a1 = hid[64 + k];
            agg[0].x = fmaf(a0, b.x, agg[0].x); agg[0].y = fmaf(a0, b.y, agg[0].y);
            agg[1].x = fmaf(a1, b.x, agg[1].x); agg[1].y = fmaf(a1, b.y, agg[1].y);
        }
        float2 bb2 = sb2v[lane];
        float2 xp[2], nx[2];
        nx[0] = nx[1] = make_float2(0.f, 0.f);
#pragma unroll
        for (int rr = 0; rr < 2; rr++) {
            float dg = (rr < nr) ? g_deg[r0 + rr] : 0.0f;
            agg[rr].x = fmaf(dg, bb2.x, agg[rr].x);
            agg[rr].y = fmaf(dg, bb2.y, agg[rr].y);
            if (rr < nr) xp[rr] = X2r[(r0 + rr) * 32 + lane];
            else         xp[rr] = make_float2(0.f, 0.f);
        }
        __syncwarp();   // all lanes done reading hid (aggH staging)

        // --- phase B: stage [x, agg] (128 per row) ---
#pragma unroll
        for (int rr = 0; rr < 2; rr++) {
            ((float2*)(in + rr * 128))[lane] = xp[rr];
            ((float2*)(in + rr * 128 + 64))[lane] = agg[rr];
        }
        __syncwarp();

        // --- phase C: hidden = silu([x,agg]@uW1 + ub1) ---
        float2 ub1p = sub1v[lane];
        float2 acc[2] = {ub1p, ub1p};
#pragma unroll 8
        for (int k = 0; k < 128; k++) {
            float2 w = sUW1[k * 32 + lane];
            float a0 = in[k];
            float a1 = in[128 + k];
            acc[0].x = fmaf(a0, w.x, acc[0].x); acc[0].y = fmaf(a0, w.y, acc[0].y);
            acc[1].x = fmaf(a1, w.x, acc[1].x); acc[1].y = fmaf(a1, w.y, acc[1].y);
        }
        __syncwarp();
#pragma unroll
        for (int rr = 0; rr < 2; rr++) {
            float2 h;
            h.x = silu(acc[rr].x);
            h.y = silu(acc[rr].y);
            ((float2*)(hid + rr * 64))[lane] = h;
        }
        __syncwarp();

        // --- phase D: o = hid@uW2 + ub2; x += o ---
        float2 ub2p = sub2v[lane];
        float2 o[2] = {ub2p, ub2p};
#pragma unroll 8
        for (int k = 0; k < 64; k++) {
            float2 w = sUW2[k * 32 + lane];
            float a0 = hid[k];
            float a1 = hid[64 + k];
            o[0].x = fmaf(a0, w.x, o[0].x); o[0].y = fmaf(a0, w.y, o[0].y);
            o[1].x = fmaf(a1, w.x, o[1].x); o[1].y = fmaf(a1, w.y, o[1].y);
        }
        for (int rr = 0; rr < nr; rr++) {
            nx[rr].x = xp[rr].x + o[rr].x;
            nx[rr].y = xp[rr].y + o[rr].y;
            X2w[(r0 + rr) * 32 + lane] = nx[rr];
        }

        // --- phase E: readout (last layer only) ---
        if (do_readout) {
            __syncwarp();
#pragma unroll
            for (int rr = 0; rr < 2; rr++)
                ((float2*)(in + rr * 64))[lane] = nx[rr];
            __syncwarp();
            float2 eb1p = seb1v[lane];
            float2 ec[2] = {eb1p, eb1p};
#pragma unroll 8
            for (int k = 0; k < 64; k++) {
                float2 w = sEW1[k * 32 + lane];
                float a0 = in[k];
                float a1 = in[64 + k];
                ec[0].x = fmaf(a0, w.x, ec[0].x); ec[0].y = fmaf(a0, w.y, ec[0].y);
                ec[1].x = fmaf(a1, w.x, ec[1].x); ec[1].y = fmaf(a1, w.y, ec[1].y);
            }
            float2 w2p = sew2v[lane];
            for (int rr = 0; rr < nr; rr++) {
                float pe = silu(ec[rr].x) * w2p.x + silu(ec[rr].y) * w2p.y;
#pragma unroll
                for (int off = 16; off > 0; off >>= 1)
                    pe += __shfl_xor_sync(0xFFFFFFFF, pe, off);
                if (lane == 0)
                    atomicAdd(&out[batch[r0 + rr]], pe + sEb2[0]);
            }
        }
        __syncwarp();
    }
}

// ------------------------------- host side ------------------------------------
extern "C" void kernel_launch(void* const* d_in, const int* in_sizes, int n_in,
                              void* d_out, int out_size) {
    const int* z = (const int*)d_in[0];
    const float* pos = (const float*)d_in[1];
    const int* ei = (const int*)d_in[2];
    const int* batch = (const int*)d_in[3];
    const float* embed = (const float*)d_in[4];
    const float* msg_w1 = (const float*)d_in[5];
    const float* msg_b1 = (const float*)d_in[6];
    const float* msg_w2 = (const float*)d_in[7];
    const float* msg_b2 = (const float*)d_in[8];
    const float* upd_w1 = (const float*)d_in[9];
    const float* upd_b1 = (const float*)d_in[10];
    const float* upd_w2 = (const float*)d_in[11];
    const float* upd_b2 = (const float*)d_in[12];
    const float* eh_w1 = (const float*)d_in[13];
    const float* eh_b1 = (const float*)d_in[14];
    const float* eh_w2 = (const float*)d_in[15];
    const float* eh_b2 = (const float*)d_in[16];
    float* out = (float*)d_out;

    int N = in_sizes[0];
    int E = in_sizes[2] / 2;

    float* p_deg; cudaGetSymbolAddress((void**)&p_deg, g_deg);

    static bool attr_set = false;
    if (!attr_set) {
        cudaFuncSetAttribute(k_node, cudaFuncAttributeMaxDynamicSharedMemorySize, 23936 * 4);
        attr_set = true;
    }

    const int TPB = 256;

    // prologue
    k_zero<<<64, TPB>>>(p_deg, N);
    k_init_x<<<1184, TPB>>>(z, embed, N);
    k_edge_attr<<<1184, TPB>>>(ei, pos, E);
    k_zero<<<1, 64>>>(out, out_size);

    for (int l = 0; l < NL; l++) {
        const float* w1 = msg_w1 + l * 136 * 64;
        const float* b1 = msg_b1 + l * 64;
        const float* w2 = msg_w2 + l * 64 * 64;
        const float* b2 = msg_b2 + l * 64;
        const float* uw1 = upd_w1 + l * 128 * 64;
        const float* ub1 = upd_b1 + l * 64;
        const float* uw2 = upd_w2 + l * 64 * 64;
        const float* ub2 = upd_b2 + l * 64;

        k_pq<<<740, TPB>>>(w1, b1, N);
        k_edge<<<1184, TPB>>>(ei, w1, E);
        k_node<<<592, TPB, 23936 * 4>>>(w2, b2, uw1, ub1, uw2, ub2,
                                        eh_w1, eh_b1, eh_w2, eh_b2,
                                        batch, out, N, (l == NL - 1) ? 1 : 0);
    }
}

// round 3
// speedup vs baseline: 1.5643x; 1.1281x over previous
#include <cuda_runtime.h>
#include <math.h>

#define H 64
#define NB 8
#define NL 2
#define MAXN 50000
#define MAXE 800000

// ---------------- scratch (device globals; no allocation allowed) ------------
__device__ __align__(256) float g_x[MAXN * H];
__device__ __align__(256) float g_P[MAXN * H];     // x@W1a + b1
__device__ __align__(256) float g_Q[MAXN * H];     // x@W1b
__device__ __align__(256) float g_aggH[MAXN * H];
__device__ __align__(256) float g_ea[MAXE * NB];
__device__ __align__(256) float g_deg[MAXN];

__device__ __forceinline__ float silu(float v) {
    return __fdividef(v, 1.0f + __expf(-v));
}

// ---------------- zero deg + out ----------------------------------------------
__global__ void k_zero2(float* __restrict__ a, int na, float* __restrict__ b, int nb) {
    int i = blockIdx.x * blockDim.x + threadIdx.x;
    int stride = gridDim.x * blockDim.x;
    for (; i < na; i += stride) a[i] = 0.0f;
    for (i = blockIdx.x * blockDim.x + threadIdx.x; i < nb; i += stride) b[i] = 0.0f;
}

// ---------------- edge_attr (E x 8) + degree: sincos + Chebyshev --------------
__global__ void k_edge_attr(const int* __restrict__ ei, const float* __restrict__ pos, int E) {
    int e = blockIdx.x * blockDim.x + threadIdx.x;
    int stride = gridDim.x * blockDim.x;
    const float PI = 3.14159265358979323846f;
    float4* ea4 = (float4*)g_ea;
    for (; e < E; e += stride) {
        int r = ei[e], c = ei[E + e];
        float dx = pos[r * 3 + 0] - pos[c * 3 + 0];
        float dy = pos[r * 3 + 1] - pos[c * 3 + 1];
        float dz = pos[r * 3 + 2] - pos[c * 3 + 2];
        float d = sqrtf(dx * dx + dy * dy + dz * dz);
        float env = 0.0f;
        if (d < 5.0f) {
            float cv = __cosf(d * (PI / 10.0f));
            env = cv * cv;
        }
        float inv = __fdividef(env, (d > 0.0f) ? d : 1.0f);
        float s1, c1;
        __sincosf(d * (PI / 5.0f), &s1, &c1);
        float twoc = 2.0f * c1;
        float sp = 0.0f, sc = s1;   // sin(k*theta) recurrence
        float v[NB];
#pragma unroll
        for (int j = 0; j < NB; j++) {
            v[j] = sc * inv;
            float sn = twoc * sc - sp;
            sp = sc; sc = sn;
        }
        ea4[e * 2 + 0] = make_float4(v[0], v[1], v[2], v[3]);
        ea4[e * 2 + 1] = make_float4(v[4], v[5], v[6], v[7]);
        atomicAdd(&g_deg[c], 1.0f);
    }
}

// ---------------- P = x@W1a + b1, Q = x@W1b; zero aggH; optional x=embed[z] ----
// lane l<16: P cols 4l..4l+3 ; lane>=16: Q cols 4(l-16)..
__global__ void k_pq(const float* __restrict__ w1, const float* __restrict__ b1,
                     const int* __restrict__ z, const float* __restrict__ embed, int N) {
    __shared__ float4 sB[64 * 32];   // [k][lane]
    __shared__ float4 sb1[16];
    __shared__ float4 sA4[8][64];    // 4 rows x 16 f4 per warp

    const float4* w1v = (const float4*)w1;
    for (int u = threadIdx.x; u < 64 * 32; u += blockDim.x) {
        int k = u >> 5, l = u & 31;
        sB[u] = (l < 16) ? w1v[k * 16 + l] : w1v[(64 + k) * 16 + (l - 16)];
    }
    if (threadIdx.x < 16) sb1[threadIdx.x] = ((const float4*)b1)[threadIdx.x];
    __syncthreads();

    int warp = threadIdx.x >> 5, lane = threadIdx.x & 31;
    int gw = (blockIdx.x * blockDim.x + threadIdx.x) >> 5;
    int nw = (gridDim.x * blockDim.x) >> 5;

    float4* P4 = (float4*)g_P;
    float4* Q4 = (float4*)g_Q;
    float4* Z4 = (float4*)g_aggH;
    float4* X4 = (float4*)g_x;
    const float4* E4 = (const float4*)embed;
    float* sA = (float*)sA4[warp];

    bool gather = (z != nullptr);

    for (int r0 = gw * 4; r0 < N; r0 += nw * 4) {
        int nr = min(4, N - r0);
        if (gather) {
            for (int t = lane; t < nr * 16; t += 32) {
                int rr = t >> 4, cc = t & 15;
                float4 v = E4[(size_t)__ldg(&z[r0 + rr]) * 16 + cc];
                sA4[warp][t] = v;
                X4[(size_t)(r0 + rr) * 16 + cc] = v;
            }
        } else {
            for (int t = lane; t < nr * 16; t += 32)
                sA4[warp][t] = X4[(size_t)r0 * 16 + t];
        }
        __syncwarp();

        float4 acc[4];
#pragma unroll
        for (int rr = 0; rr < 4; rr++)
            acc[rr] = (lane < 16) ? sb1[lane & 15] : make_float4(0.f, 0.f, 0.f, 0.f);

#pragma unroll 8
        for (int k = 0; k < 64; k++) {
            float4 b = sB[k * 32 + lane];
#pragma unroll
            for (int rr = 0; rr < 4; rr++) {
                float a = sA[rr * 64 + k];
                acc[rr].x = fmaf(a, b.x, acc[rr].x);
                acc[rr].y = fmaf(a, b.y, acc[rr].y);
                acc[rr].z = fmaf(a, b.z, acc[rr].z);
                acc[rr].w = fmaf(a, b.w, acc[rr].w);
            }
        }
        for (int rr = 0; rr < nr; rr++) {
            size_t b = (size_t)(r0 + rr) * 16;
            if (lane < 16) {
                P4[b + lane] = acc[rr];
                Z4[b + lane] = make_float4(0.f, 0.f, 0.f, 0.f);
            } else {
                Q4[b + (lane - 16)] = acc[rr];
            }
        }
        __syncwarp();
    }
}

// ---------------- edge phase: aggH[c] += silu(P[c]+Q[r]+ea@W1c) ----------------
// each half-warp handles one edge; lane covers 4 output cols (float4)
__global__ void k_edge(const int* __restrict__ ei, const float* __restrict__ w1, int E) {
    __shared__ float4 sWc[NB * 16];
    const float4* wc = (const float4*)(w1 + 128 * 64);
    for (int u = threadIdx.x; u < NB * 16; u += blockDim.x) sWc[u] = wc[u];
    __syncthreads();

    int lane = threadIdx.x & 31;
    int half = lane >> 4;
    int hl = lane & 15;
    int gw = (blockIdx.x * blockDim.x + threadIdx.x) >> 5;
    int nw = (gridDim.x * blockDim.x) >> 5;

    const float4* P4 = (const float4*)g_P;
    const float4* Q4 = (const float4*)g_Q;
    const float4* ea4 = (const float4*)g_ea;

    for (int e0 = gw * 2; e0 < E; e0 += nw * 2) {
        int e = e0 + half;
        if (e < E) {
            int r = __ldg(&ei[e]);
            int c = __ldg(&ei[E + e]);
            float4 eA = __ldg(&ea4[e * 2 + 0]);
            float4 eB = __ldg(&ea4[e * 2 + 1]);
            float4 p = P4[(size_t)c * 16 + hl];
            float4 q = Q4[(size_t)r * 16 + hl];
            float4 v;
            v.x = p.x + q.x; v.y = p.y + q.y; v.z = p.z + q.z; v.w = p.w + q.w;
            float4 w;
            w = sWc[0 * 16 + hl];
            v.x = fmaf(eA.x, w.x, v.x); v.y = fmaf(eA.x, w.y, v.y);
            v.z = fmaf(eA.x, w.z, v.z); v.w = fmaf(eA.x, w.w, v.w);
            w = sWc[1 * 16 + hl];
            v.x = fmaf(eA.y, w.x, v.x); v.y = fmaf(eA.y, w.y, v.y);
            v.z = fmaf(eA.y, w.z, v.z); v.w = fmaf(eA.y, w.w, v.w);
            w = sWc[2 * 16 + hl];
            v.x = fmaf(eA.z, w.x, v.x); v.y = fmaf(eA.z, w.y, v.y);
            v.z = fmaf(eA.z, w.z, v.z); v.w = fmaf(eA.z, w.w, v.w);
            w = sWc[3 * 16 + hl];
            v.x = fmaf(eA.w, w.x, v.x); v.y = fmaf(eA.w, w.y, v.y);
            v.z = fmaf(eA.w, w.z, v.z); v.w = fmaf(eA.w, w.w, v.w);
            w = sWc[4 * 16 + hl];
            v.x = fmaf(eB.x, w.x, v.x); v.y = fmaf(eB.x, w.y, v.y);
            v.z = fmaf(eB.x, w.z, v.z); v.w = fmaf(eB.x, w.w, v.w);
            w = sWc[5 * 16 + hl];
            v.x = fmaf(eB.y, w.x, v.x); v.y = fmaf(eB.y, w.y, v.y);
            v.z = fmaf(eB.y, w.z, v.z); v.w = fmaf(eB.y, w.w, v.w);
            w = sWc[6 * 16 + hl];
            v.x = fmaf(eB.z, w.x, v.x); v.y = fmaf(eB.z, w.y, v.y);
            v.z = fmaf(eB.z, w.z, v.z); v.w = fmaf(eB.z, w.w, v.w);
            w = sWc[7 * 16 + hl];
            v.x = fmaf(eB.w, w.x, v.x); v.y = fmaf(eB.w, w.y, v.y);
            v.z = fmaf(eB.w, w.z, v.z); v.w = fmaf(eB.w, w.w, v.w);

            float m0 = silu(v.x), m1 = silu(v.y), m2 = silu(v.z), m3 = silu(v.w);
            float* dst = g_aggH + (size_t)c * 64 + hl * 4;
            asm volatile("red.global.add.v4.f32 [%0], {%1, %2, %3, %4};"
                         :: "l"(dst), "f"(m0), "f"(m1), "f"(m2), "f"(m3) : "memory");
        }
    }
}

// ---------------- fused node phase: agg=aggH@W2+deg*b2; x+=upd; [readout] ------
__global__ void k_node(const float* __restrict__ w2, const float* __restrict__ b2,
                       const float* __restrict__ uw1, const float* __restrict__ ub1,
                       const float* __restrict__ uw2, const float* __restrict__ ub2,
                       const float* __restrict__ ew1, const float* __restrict__ eb1,
                       const float* __restrict__ ew2, const float* __restrict__ eb2,
                       const int* __restrict__ batch, float* __restrict__ out,
                       int N, int do_readout) {
    extern __shared__ float sm[];
    float2* sW2  = (float2*)sm;          // 2048 f2
    float2* sUW1 = sW2 + 2048;           // 4096 f2
    float2* sUW2 = sUW1 + 4096;          // 2048 f2
    float2* sEW1 = sUW2 + 2048;          // 2048 f2
    float2* sb2v  = sEW1 + 2048;         // 32
    float2* sub1v = sb2v + 32;
    float2* sub2v = sub1v + 32;
    float2* seb1v = sub2v + 32;
    float2* sew2v = seb1v + 32;          // 32
    float* sEb2 = sm + 20800;            // 64 floats (only [0] used)
    float* sIn  = sm + 20864;            // 8 warps * 256
    float* sHid = sm + 22912;            // 8 warps * 128

    for (int u = threadIdx.x; u < 2048; u += blockDim.x) sW2[u]  = ((const float2*)w2)[u];
    for (int u = threadIdx.x; u < 4096; u += blockDim.x) sUW1[u] = ((const float2*)uw1)[u];
    for (int u = threadIdx.x; u < 2048; u += blockDim.x) sUW2[u] = ((const float2*)uw2)[u];
    if (do_readout)
        for (int u = threadIdx.x; u < 2048; u += blockDim.x) sEW1[u] = ((const float2*)ew1)[u];
    if (threadIdx.x < 32) {
        sb2v[threadIdx.x]  = ((const float2*)b2)[threadIdx.x];
        sub1v[threadIdx.x] = ((const float2*)ub1)[threadIdx.x];
        sub2v[threadIdx.x] = ((const float2*)ub2)[threadIdx.x];
        if (do_readout) {
            seb1v[threadIdx.x] = ((const float2*)eb1)[threadIdx.x];
            sew2v[threadIdx.x] = ((const float2*)ew2)[threadIdx.x];
        }
    }
    if (threadIdx.x == 0) sEb2[0] = do_readout ? eb2[0] : 0.0f;
    __syncthreads();

    int warp = threadIdx.x >> 5, lane = threadIdx.x & 31;
    int gw = (blockIdx.x * blockDim.x + threadIdx.x) >> 5;
    int nw = (gridDim.x * blockDim.x) >> 5;
    float* in  = sIn + warp * 256;
    float* hid = sHid + warp * 128;

    const float2* X2r = (const float2*)g_x;
    float2* X2w = (float2*)g_x;
    const float2* AG2 = (const float2*)g_aggH;

    for (int r0 = gw * 2; r0 < N; r0 += nw * 2) {
        int nr = min(2, N - r0);

        // --- phase A: agg = aggH @ W2 + deg*b2 ---
        for (int t = lane; t < nr * 32; t += 32)
            ((float2*)hid)[t] = AG2[r0 * 32 + t];
        __syncwarp();

        float2 agg[2] = {make_float2(0.f, 0.f), make_float2(0.f, 0.f)};
#pragma unroll 8
        for (int k = 0; k < 64; k++) {
            float2 b = sW2[k * 32 + lane];
            float a0 = hid[k];
            float a1 = hid[64 + k];
            agg[0].x = fmaf(a0, b.x, agg[0].x); agg[0].y = fmaf(a0, b.y, agg[0].y);
            agg[1].x = fmaf(a1, b.x, agg[1].x); agg[1].y = fmaf(a1, b.y, agg[1].y);
        }
        float2 bb2 = sb2v[lane];
        float2 xp[2], nx[2];
        nx[0] = nx[1] = make_float2(0.f, 0.f);
#pragma unroll
        for (int rr = 0; rr < 2; rr++) {
            float dg = (rr < nr) ? g_deg[r0 + rr] : 0.0f;
            agg[rr].x = fmaf(dg, bb2.x, agg[rr].x);
            agg[rr].y = fmaf(dg, bb2.y, agg[rr].y);
            if (rr < nr) xp[rr] = X2r[(r0 + rr) * 32 + lane];
            else         xp[rr] = make_float2(0.f, 0.f);
        }
        __syncwarp();   // all lanes done reading hid (aggH staging)

        // --- phase B: stage [x, agg] (128 per row) ---
#pragma unroll
        for (int rr = 0; rr < 2; rr++) {
            ((float2*)(in + rr * 128))[lane] = xp[rr];
            ((float2*)(in + rr * 128 + 64))[lane] = agg[rr];
        }
        __syncwarp();

        // --- phase C: hidden = silu([x,agg]@uW1 + ub1) ---
        float2 ub1p = sub1v[lane];
        float2 acc[2] = {ub1p, ub1p};
#pragma unroll 8
        for (int k = 0; k < 128; k++) {
            float2 w = sUW1[k * 32 + lane];
            float a0 = in[k];
            float a1 = in[128 + k];
            acc[0].x = fmaf(a0, w.x, acc[0].x); acc[0].y = fmaf(a0, w.y, acc[0].y);
            acc[1].x = fmaf(a1, w.x, acc[1].x); acc[1].y = fmaf(a1, w.y, acc[1].y);
        }
        __syncwarp();
#pragma unroll
        for (int rr = 0; rr < 2; rr++) {
            float2 h;
            h.x = silu(acc[rr].x);
            h.y = silu(acc[rr].y);
            ((float2*)(hid + rr * 64))[lane] = h;
        }
        __syncwarp();

        // --- phase D: o = hid@uW2 + ub2; x += o ---
        float2 ub2p = sub2v[lane];
        float2 o[2] = {ub2p, ub2p};
#pragma unroll 8
        for (int k = 0; k < 64; k++) {
            float2 w = sUW2[k * 32 + lane];
            float a0 = hid[k];
            float a1 = hid[64 + k];
            o[0].x = fmaf(a0, w.x, o[0].x); o[0].y = fmaf(a0, w.y, o[0].y);
            o[1].x = fmaf(a1, w.x, o[1].x); o[1].y = fmaf(a1, w.y, o[1].y);
        }
        for (int rr = 0; rr < nr; rr++) {
            nx[rr].x = xp[rr].x + o[rr].x;
            nx[rr].y = xp[rr].y + o[rr].y;
            X2w[(r0 + rr) * 32 + lane] = nx[rr];
        }

        // --- phase E: readout (last layer only) ---
        if (do_readout) {
            __syncwarp();
#pragma unroll
            for (int rr = 0; rr < 2; rr++)
                ((float2*)(in + rr * 64))[lane] = nx[rr];
            __syncwarp();
            float2 eb1p = seb1v[lane];
            float2 ec[2] = {eb1p, eb1p};
#pragma unroll 8
            for (int k = 0; k < 64; k++) {
                float2 w = sEW1[k * 32 + lane];
                float a0 = in[k];
                float a1 = in[64 + k];
                ec[0].x = fmaf(a0, w.x, ec[0].x); ec[0].y = fmaf(a0, w.y, ec[0].y);
                ec[1].x = fmaf(a1, w.x, ec[1].x); ec[1].y = fmaf(a1, w.y, ec[1].y);
            }
            float2 w2p = sew2v[lane];
            for (int rr = 0; rr < nr; rr++) {
                float pe = silu(ec[rr].x) * w2p.x + silu(ec[rr].y) * w2p.y;
#pragma unroll
                for (int off = 16; off > 0; off >>= 1)
                    pe += __shfl_xor_sync(0xFFFFFFFF, pe, off);
                if (lane == 0)
                    atomicAdd(&out[batch[r0 + rr]], pe + sEb2[0]);
            }
        }
        __syncwarp();
    }
}

// ------------------------------- host side ------------------------------------
extern "C" void kernel_launch(void* const* d_in, const int* in_sizes, int n_in,
                              void* d_out, int out_size) {
    const int* z = (const int*)d_in[0];
    const float* pos = (const float*)d_in[1];
    const int* ei = (const int*)d_in[2];
    const int* batch = (const int*)d_in[3];
    const float* embed = (const float*)d_in[4];
    const float* msg_w1 = (const float*)d_in[5];
    const float* msg_b1 = (const float*)d_in[6];
    const float* msg_w2 = (const float*)d_in[7];
    const float* msg_b2 = (const float*)d_in[8];
    const float* upd_w1 = (const float*)d_in[9];
    const float* upd_b1 = (const float*)d_in[10];
    const float* upd_w2 = (const float*)d_in[11];
    const float* upd_b2 = (const float*)d_in[12];
    const float* eh_w1 = (const float*)d_in[13];
    const float* eh_b1 = (const float*)d_in[14];
    const float* eh_w2 = (const float*)d_in[15];
    const float* eh_b2 = (const float*)d_in[16];
    float* out = (float*)d_out;

    int N = in_sizes[0];
    int E = in_sizes[2] / 2;

    float* p_deg; cudaGetSymbolAddress((void**)&p_deg, g_deg);

    static bool attr_set = false;
    if (!attr_set) {
        cudaFuncSetAttribute(k_node, cudaFuncAttributeMaxDynamicSharedMemorySize, 23936 * 4);
        attr_set = true;
    }

    const int TPB = 256;

    // prologue (ordered so the profiler's slot #4 lands on k_edge of layer 0)
    k_zero2<<<128, TPB>>>(p_deg, N, out, out_size);
    k_edge_attr<<<1184, TPB>>>(ei, pos, E);

    for (int l = 0; l < NL; l++) {
        const float* w1 = msg_w1 + l * 136 * 64;
        const float* b1 = msg_b1 + l * 64;
        const float* w2 = msg_w2 + l * 64 * 64;
        const float* b2 = msg_b2 + l * 64;
        const float* uw1 = upd_w1 + l * 128 * 64;
        const float* ub1 = upd_b1 + l * 64;
        const float* uw2 = upd_w2 + l * 64 * 64;
        const float* ub2 = upd_b2 + l * 64;

        k_pq<<<740, TPB>>>(w1, b1, (l == 0) ? z : nullptr,
                           (l == 0) ? embed : nullptr, N);
        k_edge<<<1184, TPB>>>(ei, w1, E);
        k_node<<<592, TPB, 23936 * 4>>>(w2, b2, uw1, ub1, uw2, ub2,
                                        eh_w1, eh_b1, eh_w2, eh_b2,
                                        batch, out, N, (l == NL - 1) ? 1 : 0);
    }
}